// round 14
// baseline (speedup 1.0000x reference)
#include <cuda_runtime.h>
#include <math.h>
#include <stdint.h>

#define BB 16
#define NN 1024
#define IND 256
#define HH 4
#define DD 64
#define HD 256
#define EPSV 1e-5f
#define NEGBIG -1.0e30f

typedef unsigned long long u64;
typedef unsigned int u32;
typedef unsigned short u16;

// Scratch (no allocations allowed)
__device__ u16 g_hbhi[BB * NN * HD];  // h high bf16 plane
__device__ u16 g_hblo[BB * NN * HD];  // h low  bf16 plane
__device__ float g_src[BB * NN * HH];
__device__ float g_dst[BB * NN * HH];
__device__ float g_att[BB * NN * HD];

// ---------------- bf16 split helpers ----------------
__device__ __forceinline__ float bhi(float x) {
    return __uint_as_float(__float_as_uint(x) & 0xffff0000u);
}
// pack (even, odd) -> bf16x2 (even element in low half)
__device__ __forceinline__ u32 cvt2(float e, float o) {
    u32 r;
    asm("cvt.rn.bf16x2.f32 %0, %1, %2;" : "=r"(r) : "f"(o), "f"(e));
    return r;
}

// ---------------- mma.sync / ldmatrix / cp.async (sm_80+ baseline) --------
__device__ __forceinline__ u32 smem_u32(const void* p) {
    return (u32)__cvta_generic_to_shared(p);
}
__device__ __forceinline__ void ldsm_x4(u32* r, u32 addr) {
    asm volatile("ldmatrix.sync.aligned.m8n8.x4.shared.b16 {%0,%1,%2,%3}, [%4];"
                 : "=r"(r[0]), "=r"(r[1]), "=r"(r[2]), "=r"(r[3]) : "r"(addr));
}
__device__ __forceinline__ void ldsm_x4t(u32* r, u32 addr) {
    asm volatile("ldmatrix.sync.aligned.m8n8.x4.trans.shared.b16 {%0,%1,%2,%3}, [%4];"
                 : "=r"(r[0]), "=r"(r[1]), "=r"(r[2]), "=r"(r[3]) : "r"(addr));
}
__device__ __forceinline__ void mma16816(float* c, const u32* a, u32 b0, u32 b1) {
    asm volatile(
        "mma.sync.aligned.m16n8k16.row.col.f32.bf16.bf16.f32 "
        "{%0,%1,%2,%3}, {%4,%5,%6,%7}, {%8,%9}, {%0,%1,%2,%3};"
        : "+f"(c[0]), "+f"(c[1]), "+f"(c[2]), "+f"(c[3])
        : "r"(a[0]), "r"(a[1]), "r"(a[2]), "r"(a[3]), "r"(b0), "r"(b1));
}
__device__ __forceinline__ void cp16(u32 s, const void* g) {
    asm volatile("cp.async.cg.shared.global [%0], [%1], 16;" :: "r"(s), "l"(g));
}
__device__ __forceinline__ void cp_commit() {
    asm volatile("cp.async.commit_group;" ::: "memory");
}
__device__ __forceinline__ void cp_wait0() {
    asm volatile("cp.async.wait_group 0;" ::: "memory");
}

// convert 8 fp32 -> bf16 hi/lo planes (uint4 each)
__device__ __forceinline__ void stage8(u16* dhi, u16* dlo, float4 a, float4 b) {
    float v[8] = {a.x, a.y, a.z, a.w, b.x, b.y, b.z, b.w};
    u32 hw[4], lw[4];
#pragma unroll
    for (int g = 0; g < 4; g++) {
        float h0 = bhi(v[2 * g]), h1 = bhi(v[2 * g + 1]);
        hw[g] = cvt2(h0, h1);
        lw[g] = cvt2(v[2 * g] - h0, v[2 * g + 1] - h1);
    }
    *(uint4*)dhi = make_uint4(hw[0], hw[1], hw[2], hw[3]);
    *(uint4*)dlo = make_uint4(lw[0], lw[1], lw[2], lw[3]);
}

// ---------------------------------------------------------------------------
// Kernel 1: h = x @ W via split-bf16 mma.sync, DOUBLE-BUFFERED (1 sync/slab).
// Block = 128 rows x 128 cols (2 heads), 256 threads / 8 warps.
// ---------------------------------------------------------------------------
__global__ __launch_bounds__(256) void gemm_k(const float* __restrict__ A,
                                              const float* __restrict__ Wm,
                                              const float* __restrict__ asrc,
                                              const float* __restrict__ adst) {
    __shared__ __align__(16) u16 Xhi[2][128][24];
    __shared__ __align__(16) u16 Xlo[2][128][24];
    __shared__ __align__(16) u16 Whi[2][16][136];
    __shared__ __align__(16) u16 Wlo[2][16][136];

    int bm = blockIdx.x, bn = blockIdx.y;
    int tid = threadIdx.x;
    int lane = tid & 31, wid = tid >> 5;
    int xr = tid >> 1, xc = (tid & 1) * 8;
    int wr = tid >> 4, wc = (tid & 15) * 8;
    const float* Ap = A + (size_t)(bm * 128 + xr) * IND + xc;
    const float* Bp = Wm + (size_t)wr * HD + bn * 128 + wc;

    float c[16][4] = {};
    int m0 = wid * 16;
    int lr = lane & 15, lc = (lane >> 4) * 8;

    // prologue: stage slab 0, load slab 1 regs
    float4 xa = ((const float4*)Ap)[0], xb = ((const float4*)Ap)[1];
    float4 wa = ((const float4*)Bp)[0], wb = ((const float4*)Bp)[1];
    stage8(&Xhi[0][xr][xc], &Xlo[0][xr][xc], xa, xb);
    stage8(&Whi[0][wr][wc], &Wlo[0][wr][wc], wa, wb);
    xa = ((const float4*)(Ap + 16))[0];
    xb = ((const float4*)(Ap + 16))[1];
    wa = ((const float4*)(Bp + (size_t)16 * HD))[0];
    wb = ((const float4*)(Bp + (size_t)16 * HD))[1];
    __syncthreads();

    for (int s = 0; s < 16; s++) {
        int cur = s & 1;
        // store slab s+1 into the other buffer (before mma; protected by prev sync)
        if (s < 15) {
            stage8(&Xhi[cur ^ 1][xr][xc], &Xlo[cur ^ 1][xr][xc], xa, xb);
            stage8(&Whi[cur ^ 1][wr][wc], &Wlo[cur ^ 1][wr][wc], wa, wb);
        }
        // issue LDGs for slab s+2 (land during mma)
        if (s < 14) {
            xa = ((const float4*)(Ap + (s + 2) * 16))[0];
            xb = ((const float4*)(Ap + (s + 2) * 16))[1];
            wa = ((const float4*)(Bp + (size_t)(s + 2) * 16 * HD))[0];
            wb = ((const float4*)(Bp + (size_t)(s + 2) * 16 * HD))[1];
        }
        // mma on buffer cur
        u32 ahi[4], alo[4];
        ldsm_x4(ahi, smem_u32(&Xhi[cur][m0 + lr][lc]));
        ldsm_x4(alo, smem_u32(&Xlo[cur][m0 + lr][lc]));
#pragma unroll
        for (int half = 0; half < 2; half++) {
            u32 bh[16], bl[16];
#pragma unroll
            for (int g = 0; g < 4; g++) {
                ldsm_x4t(bh + 4 * g, smem_u32(&Whi[cur][lr][half * 64 + g * 16 + lc]));
                ldsm_x4t(bl + 4 * g, smem_u32(&Wlo[cur][lr][half * 64 + g * 16 + lc]));
            }
#pragma unroll
            for (int n2 = 0; n2 < 8; n2++) {
                int nb = half * 8 + n2;
                mma16816(c[nb], ahi, bh[2 * n2], bh[2 * n2 + 1]);
                mma16816(c[nb], alo, bh[2 * n2], bh[2 * n2 + 1]);
                mma16816(c[nb], ahi, bl[2 * n2], bl[2 * n2 + 1]);
            }
        }
        __syncthreads();
    }

    // --- epilogue: h planes + src/dst dots from fragments (unchanged) ---
    int r0 = lane >> 2, col0 = (lane & 3) * 2;
    int row0 = bm * 128 + m0 + r0;
    int row1 = row0 + 8;
    float ps[2][2] = {}, pd[2][2] = {};
#pragma unroll
    for (int nb = 0; nb < 16; nb++) {
        int hdl = nb >> 3;
        int cloc = (nb & 7) * 8 + col0;
        int hd = bn * 2 + hdl;
        float as0 = asrc[hd * DD + cloc], as1 = asrc[hd * DD + cloc + 1];
        float ad0 = adst[hd * DD + cloc], ad1 = adst[hd * DD + cloc + 1];
        float v0 = c[nb][0], v1 = c[nb][1], v2 = c[nb][2], v3 = c[nb][3];
        ps[0][hdl] += v0 * as0 + v1 * as1;
        ps[1][hdl] += v2 * as0 + v3 * as1;
        pd[0][hdl] += v0 * ad0 + v1 * ad1;
        pd[1][hdl] += v2 * ad0 + v3 * ad1;
        int gcol = bn * 128 + nb * 8 + col0;
        float h0 = bhi(v0), h1 = bhi(v1);
        *(u32*)&g_hbhi[(size_t)row0 * HD + gcol] = cvt2(h0, h1);
        *(u32*)&g_hblo[(size_t)row0 * HD + gcol] = cvt2(v0 - h0, v1 - h1);
        float h2 = bhi(v2), h3 = bhi(v3);
        *(u32*)&g_hbhi[(size_t)row1 * HD + gcol] = cvt2(h2, h3);
        *(u32*)&g_hblo[(size_t)row1 * HD + gcol] = cvt2(v2 - h2, v3 - h3);
    }
#pragma unroll
    for (int r = 0; r < 2; r++)
#pragma unroll
        for (int h = 0; h < 2; h++) {
            ps[r][h] += __shfl_xor_sync(0xffffffffu, ps[r][h], 1);
            ps[r][h] += __shfl_xor_sync(0xffffffffu, ps[r][h], 2);
            pd[r][h] += __shfl_xor_sync(0xffffffffu, pd[r][h], 1);
            pd[r][h] += __shfl_xor_sync(0xffffffffu, pd[r][h], 2);
        }
    if ((lane & 3) == 0) {
#pragma unroll
        for (int h = 0; h < 2; h++) {
            g_src[(size_t)row0 * HH + bn * 2 + h] = ps[0][h];
            g_src[(size_t)row1 * HH + bn * 2 + h] = ps[1][h];
            g_dst[(size_t)row0 * HH + bn * 2 + h] = pd[0][h];
            g_dst[(size_t)row1 * HH + bn * 2 + h] = pd[1][h];
        }
    }
}

// ---------------------------------------------------------------------------
// Kernel 2: attention via mma.sync bf16 (split hi/lo, 3 passes).
// cp.async double-buffered V + adj; dst double-buffered; 2 syncs/tile.
// Dynamic smem layout (90880 B total):
//   adjS [2][64][68] int   @ 0       (34816)
//   Vhi  [2][64][72] u16   @ 34816   (18432)
//   Vlo  [2][64][72] u16   @ 53248   (18432)
//   Phi  [64][72]    u16   @ 71680   (9216)
//   Plo  [64][72]    u16   @ 80896   (9216)
//   dst  [2][64]     f32   @ 90112   (512)
//   l    [64]        f32   @ 90624   (256)
// ---------------------------------------------------------------------------
#define SMEM_ATTN 90880

__device__ __forceinline__ void attn_stage_async(
    const int* __restrict__ adj, int b, int hh, int i0, int j0, int tid,
    u32 adjS_b, u32 vhi_b, u32 vlo_b) {
    int vr = tid >> 2;
    int c2 = (tid & 3) * 2;
    const u16* gh = g_hbhi + (size_t)(b * NN + j0 + vr) * HD + hh * 64;
    const u16* gl = g_hblo + (size_t)(b * NN + j0 + vr) * HD + hh * 64;
    u32 sh = vhi_b + vr * 144;
    u32 sl = vlo_b + vr * 144;
    cp16(sh + c2 * 16, gh + c2 * 8);
    cp16(sh + c2 * 16 + 16, gh + c2 * 8 + 8);
    cp16(sl + c2 * 16, gl + c2 * 8);
    cp16(sl + c2 * 16 + 16, gl + c2 * 8 + 8);
    const int* ga = adj + (size_t)(b * NN + i0 + vr) * NN + j0 + (tid & 3) * 16;
    u32 sa = adjS_b + vr * 272 + (tid & 3) * 64;
    cp16(sa, ga);
    cp16(sa + 16, ga + 4);
    cp16(sa + 32, ga + 8);
    cp16(sa + 48, ga + 12);
    cp_commit();
}

__global__ __launch_bounds__(256) void attn_k(const int* __restrict__ adj,
                                              const int* __restrict__ mask) {
    extern __shared__ __align__(16) unsigned char s_raw[];
    int* adjS = (int*)(s_raw);
    u16* VhiB = (u16*)(s_raw + 34816);
    u16* VloB = (u16*)(s_raw + 53248);
    u16* PhiS = (u16*)(s_raw + 71680);
    u16* PloS = (u16*)(s_raw + 80896);
    float* dstS = (float*)(s_raw + 90112);
    float* s_l = (float*)(s_raw + 90624);

    int it = blockIdx.x, hh = blockIdx.y, b = blockIdx.z;
    int i0 = it * 64;
    int tid = threadIdx.x;
    int lane = tid & 31, wid = tid >> 5;
    int ti = tid >> 2, q = tid & 3;

    u32 adjS_u = smem_u32(adjS);
    u32 vhi_u = smem_u32(VhiB);
    u32 vlo_u = smem_u32(VloB);

    int gi = b * NN + i0 + ti;
    float srcv = mask[gi] > 0 ? g_src[(size_t)gi * HH + hh] : NEGBIG;
    float lsum = 0.f;

    float c[4][4] = {};
    int m0 = (wid & 3) * 16, n0 = (wid >> 2) * 32;
    int lr = lane & 15, lc = (lane >> 4) * 8;

    // prologue: async stage tile 0 into buf 0, stage dst(0)
    attn_stage_async(adj, b, hh, i0, 0, tid, adjS_u, vhi_u, vlo_u);
    if (tid < 64) {
        int gj = b * NN + tid;
        float d = g_dst[(size_t)gj * HH + hh];
        dstS[tid] = mask[gj] > 0 ? d : NEGBIG;
    }
    cp_wait0();
    __syncthreads();

    for (int t = 0; t < 16; t++) {
        int buf = t & 1;
        // issue next tile's async loads + stage next dst (other buffers)
        if (t < 15) {
            attn_stage_async(adj, b, hh, i0, (t + 1) * 64, tid,
                             adjS_u + 17408 * (buf ^ 1),
                             vhi_u + 9216 * (buf ^ 1),
                             vlo_u + 9216 * (buf ^ 1));
            if (tid < 64) {
                int gj = b * NN + (t + 1) * 64 + tid;
                float d = g_dst[(size_t)gj * HH + hh];
                dstS[(buf ^ 1) * 64 + tid] = mask[gj] > 0 ? d : NEGBIG;
            }
        }

        // --- score: p = valid ? exp(leaky(src+dst)) : 0 ; split -> Phi/Plo
        {
            const int4* ar4 = (const int4*)(adjS + buf * 4352 + ti * 68 + q * 16);
            int4 aj0 = ar4[0], aj1 = ar4[1], aj2 = ar4[2], aj3 = ar4[3];
            const float4* dp = (const float4*)(dstS + buf * 64 + q * 16);
            float4 d0 = dp[0], d1 = dp[1], d2 = dp[2], d3 = dp[3];
            float p[16];
            float e;
#define SC4(AJ, DV, K)                                                        \
            e = srcv + DV.x; e = fmaxf(e, 0.2f * e); p[K+0] = AJ.x > 0 ? __expf(e) : 0.f; \
            e = srcv + DV.y; e = fmaxf(e, 0.2f * e); p[K+1] = AJ.y > 0 ? __expf(e) : 0.f; \
            e = srcv + DV.z; e = fmaxf(e, 0.2f * e); p[K+2] = AJ.z > 0 ? __expf(e) : 0.f; \
            e = srcv + DV.w; e = fmaxf(e, 0.2f * e); p[K+3] = AJ.w > 0 ? __expf(e) : 0.f;
            SC4(aj0, d0, 0) SC4(aj1, d1, 4) SC4(aj2, d2, 8) SC4(aj3, d3, 12)
#undef SC4
#pragma unroll
            for (int k = 0; k < 16; k++) lsum += p[k];
            u32 hw[8], lw[8];
#pragma unroll
            for (int g = 0; g < 8; g++) {
                float h0 = bhi(p[2 * g]), h1 = bhi(p[2 * g + 1]);
                hw[g] = cvt2(h0, h1);
                lw[g] = cvt2(p[2 * g] - h0, p[2 * g + 1] - h1);
            }
            u16* ph = PhiS + ti * 72 + q * 16;
            u16* pl = PloS + ti * 72 + q * 16;
            ((uint4*)ph)[0] = make_uint4(hw[0], hw[1], hw[2], hw[3]);
            ((uint4*)ph)[1] = make_uint4(hw[4], hw[5], hw[6], hw[7]);
            ((uint4*)pl)[0] = make_uint4(lw[0], lw[1], lw[2], lw[3]);
            ((uint4*)pl)[1] = make_uint4(lw[4], lw[5], lw[6], lw[7]);
        }
        __syncthreads();   // P ready (dst(t+1) also written)

        // --- mma: 4 k-steps of 16, 3 passes (hi.hi, lo.hi, hi.lo) ---
        u32 vbase_h = vhi_u + 9216 * buf;
        u32 vbase_l = vlo_u + 9216 * buf;
#pragma unroll
        for (int ks = 0; ks < 4; ks++) {
            u32 ahi[4], alo[4], bh[8], bl[8];
            ldsm_x4(ahi, smem_u32(PhiS + (m0 + lr) * 72 + ks * 16 + lc));
            ldsm_x4(alo, smem_u32(PloS + (m0 + lr) * 72 + ks * 16 + lc));
            int br = ks * 16 + lr;
            ldsm_x4t(bh,     vbase_h + br * 144 + (n0 + lc) * 2);
            ldsm_x4t(bh + 4, vbase_h + br * 144 + (n0 + 16 + lc) * 2);
            ldsm_x4t(bl,     vbase_l + br * 144 + (n0 + lc) * 2);
            ldsm_x4t(bl + 4, vbase_l + br * 144 + (n0 + 16 + lc) * 2);
#pragma unroll
            for (int nb = 0; nb < 4; nb++) {
                mma16816(c[nb], ahi, bh[2 * nb], bh[2 * nb + 1]);
                mma16816(c[nb], alo, bh[2 * nb], bh[2 * nb + 1]);
                mma16816(c[nb], ahi, bl[2 * nb], bl[2 * nb + 1]);
            }
        }
        cp_wait0();        // tile t+1 async data landed
        __syncthreads();   // everyone done with buf; buf^1 valid for all
    }

    // --- final l reduction + epilogue ---
    lsum += __shfl_xor_sync(0xffffffffu, lsum, 1);
    lsum += __shfl_xor_sync(0xffffffffu, lsum, 2);
    if (q == 0) s_l[ti] = lsum;
    __syncthreads();
    {
        int r0 = lane >> 2, col0 = (lane & 3) * 2;
        float l0 = s_l[m0 + r0], l1 = s_l[m0 + r0 + 8];
        float inv0 = l0 > 0.f ? 1.0f / l0 : 0.f;
        float inv1 = l1 > 0.f ? 1.0f / l1 : 0.f;
        float* ob = g_att + (size_t)(b * NN + i0 + m0 + r0) * HD + hh * 64 + n0 + col0;
#pragma unroll
        for (int nb = 0; nb < 4; nb++) {
            *(float2*)(ob + nb * 8) = make_float2(c[nb][0] * inv0, c[nb][1] * inv0);
            *(float2*)(ob + 8 * HD + nb * 8) = make_float2(c[nb][2] * inv1, c[nb][3] * inv1);
        }
    }
}

// ---------------------------------------------------------------------------
// Kernel 3: LayerNorm. 32 threads/row, warp-shfl only.  (unchanged)
// ---------------------------------------------------------------------------
__global__ __launch_bounds__(256) void ln_k(const int* __restrict__ mask,
                                            const float* __restrict__ gamma,
                                            const float* __restrict__ beta,
                                            float* __restrict__ out) {
    int row = blockIdx.x * 8 + (threadIdx.x >> 5);
    int lane = threadIdx.x & 31;
    float mf = mask[row] > 0 ? 1.f : 0.f;
    const float* ar = g_att + (size_t)row * HD + lane * 8;
    float4 v0 = ((const float4*)ar)[0];
    float4 v1 = ((const float4*)ar)[1];
    v0.x *= mf; v0.y *= mf; v0.z *= mf; v0.w *= mf;
    v1.x *= mf; v1.y *= mf; v1.z *= mf; v1.w *= mf;
    float s = v0.x + v0.y + v0.z + v0.w + v1.x + v1.y + v1.z + v1.w;
    float s2 = v0.x * v0.x + v0.y * v0.y + v0.z * v0.z + v0.w * v0.w
             + v1.x * v1.x + v1.y * v1.y + v1.z * v1.z + v1.w * v1.w;
#pragma unroll
    for (int o = 16; o > 0; o >>= 1) {
        s += __shfl_xor_sync(0xffffffffu, s, o);
        s2 += __shfl_xor_sync(0xffffffffu, s2, o);
    }
    float mu = s * (1.0f / HD);
    float var = s2 * (1.0f / HD) - mu * mu;
    float rstd = rsqrtf(var + EPSV);
    float4 g0 = ((const float4*)(gamma + lane * 8))[0];
    float4 g1 = ((const float4*)(gamma + lane * 8))[1];
    float4 b0 = ((const float4*)(beta + lane * 8))[0];
    float4 b1 = ((const float4*)(beta + lane * 8))[1];
    float* o = out + (size_t)row * HD + lane * 8;
    ((float4*)o)[0] = make_float4((v0.x - mu) * rstd * g0.x + b0.x,
                                  (v0.y - mu) * rstd * g0.y + b0.y,
                                  (v0.z - mu) * rstd * g0.z + b0.z,
                                  (v0.w - mu) * rstd * g0.w + b0.w);
    ((float4*)o)[1] = make_float4((v1.x - mu) * rstd * g1.x + b1.x,
                                  (v1.y - mu) * rstd * g1.y + b1.y,
                                  (v1.z - mu) * rstd * g1.z + b1.z,
                                  (v1.w - mu) * rstd * g1.w + b1.w);
}

// ---------------------------------------------------------------------------
extern "C" void kernel_launch(void* const* d_in, const int* in_sizes, int n_in,
                              void* d_out, int out_size) {
    const float* x = (const float*)d_in[0];
    const int* adj = (const int*)d_in[1];
    const int* mask = (const int*)d_in[2];
    const float* Wm = (const float*)d_in[3];
    const float* a_src = (const float*)d_in[4];
    const float* a_dst = (const float*)d_in[5];
    const float* gamma = (const float*)d_in[6];
    const float* beta = (const float*)d_in[7];
    float* out = (float*)d_out;

    cudaFuncSetAttribute(attn_k, cudaFuncAttributeMaxDynamicSharedMemorySize,
                         SMEM_ATTN);

    dim3 gg(BB * NN / 128, HD / 128);
    gemm_k<<<gg, 256>>>(x, Wm, a_src, a_dst);
    dim3 ga(NN / 64, HH, BB);
    attn_k<<<ga, 256, SMEM_ATTN>>>(adj, mask);
    ln_k<<<BB * NN / 8, 256>>>(mask, gamma, beta, out);
}

// round 15
// speedup vs baseline: 1.3566x; 1.3566x over previous
#include <cuda_runtime.h>
#include <math.h>
#include <stdint.h>

#define BB 16
#define NN 1024
#define IND 256
#define HH 4
#define DD 64
#define HD 256
#define EPSV 1e-5f
#define NEGBIG -1.0e30f

typedef unsigned long long u64;
typedef unsigned int u32;
typedef unsigned short u16;

// Scratch (no allocations allowed)
__device__ u16 g_hbhi[BB * NN * HD];  // h high bf16 plane
__device__ u16 g_hblo[BB * NN * HD];  // h low  bf16 plane
__device__ float g_src[BB * NN * HH];
__device__ float g_dst[BB * NN * HH];
__device__ float g_att[BB * NN * HD];

// ---------------- bf16 split helpers ----------------
__device__ __forceinline__ float bhi(float x) {
    return __uint_as_float(__float_as_uint(x) & 0xffff0000u);
}
// pack (even, odd) -> bf16x2 (even element in low half)
__device__ __forceinline__ u32 cvt2(float e, float o) {
    u32 r;
    asm("cvt.rn.bf16x2.f32 %0, %1, %2;" : "=r"(r) : "f"(o), "f"(e));
    return r;
}

// ---------------- mma.sync / ldmatrix helpers (sm_80+ baseline PTX) --------
__device__ __forceinline__ u32 smem_u32(const void* p) {
    return (u32)__cvta_generic_to_shared(p);
}
__device__ __forceinline__ void ldsm_x4(u32* r, u32 addr) {
    asm volatile("ldmatrix.sync.aligned.m8n8.x4.shared.b16 {%0,%1,%2,%3}, [%4];"
                 : "=r"(r[0]), "=r"(r[1]), "=r"(r[2]), "=r"(r[3]) : "r"(addr));
}
__device__ __forceinline__ void ldsm_x4t(u32* r, u32 addr) {
    asm volatile("ldmatrix.sync.aligned.m8n8.x4.trans.shared.b16 {%0,%1,%2,%3}, [%4];"
                 : "=r"(r[0]), "=r"(r[1]), "=r"(r[2]), "=r"(r[3]) : "r"(addr));
}
__device__ __forceinline__ void mma16816(float* c, const u32* a, u32 b0, u32 b1) {
    asm volatile(
        "mma.sync.aligned.m16n8k16.row.col.f32.bf16.bf16.f32 "
        "{%0,%1,%2,%3}, {%4,%5,%6,%7}, {%8,%9}, {%0,%1,%2,%3};"
        : "+f"(c[0]), "+f"(c[1]), "+f"(c[2]), "+f"(c[3])
        : "r"(a[0]), "r"(a[1]), "r"(a[2]), "r"(a[3]), "r"(b0), "r"(b1));
}

// ---------------------------------------------------------------------------
// Kernel 1: h = x @ W via split-bf16 mma.sync (R11 version, 35us measured).
// Block = 128 rows x 128 cols (2 heads), 256 threads / 8 warps.
// ---------------------------------------------------------------------------
__global__ __launch_bounds__(256) void gemm_k(const float* __restrict__ A,
                                              const float* __restrict__ Wm,
                                              const float* __restrict__ asrc,
                                              const float* __restrict__ adst) {
    __shared__ __align__(16) u16 Xhi[128][24];   // [row][k] (+pad)
    __shared__ __align__(16) u16 Xlo[128][24];
    __shared__ __align__(16) u16 Whi[16][136];   // [k][n] (+pad)
    __shared__ __align__(16) u16 Wlo[16][136];

    int bm = blockIdx.x, bn = blockIdx.y;
    int tid = threadIdx.x;
    int lane = tid & 31, wid = tid >> 5;
    int xr = tid >> 1, xc = (tid & 1) * 8;
    int wr = tid >> 4, wc = (tid & 15) * 8;
    const float* Ap = A + (size_t)(bm * 128 + xr) * IND + xc;
    const float* Bp = Wm + (size_t)wr * HD + bn * 128 + wc;

    float c[16][4] = {};
    int m0 = wid * 16;
    int lr = lane & 15, lc = (lane >> 4) * 8;

    float4 xa = ((const float4*)Ap)[0], xb = ((const float4*)Ap)[1];
    float4 wa = ((const float4*)Bp)[0], wb = ((const float4*)Bp)[1];

    for (int s = 0; s < 16; s++) {
        // stage current slab: convert fp32 -> bf16 hi/lo, write smem
        {
            float v[8] = {xa.x, xa.y, xa.z, xa.w, xb.x, xb.y, xb.z, xb.w};
            u32 hw[4], lw[4];
#pragma unroll
            for (int g = 0; g < 4; g++) {
                float h0 = bhi(v[2 * g]), h1 = bhi(v[2 * g + 1]);
                hw[g] = cvt2(h0, h1);
                lw[g] = cvt2(v[2 * g] - h0, v[2 * g + 1] - h1);
            }
            *(uint4*)&Xhi[xr][xc] = make_uint4(hw[0], hw[1], hw[2], hw[3]);
            *(uint4*)&Xlo[xr][xc] = make_uint4(lw[0], lw[1], lw[2], lw[3]);
            float w[8] = {wa.x, wa.y, wa.z, wa.w, wb.x, wb.y, wb.z, wb.w};
#pragma unroll
            for (int g = 0; g < 4; g++) {
                float h0 = bhi(w[2 * g]), h1 = bhi(w[2 * g + 1]);
                hw[g] = cvt2(h0, h1);
                lw[g] = cvt2(w[2 * g] - h0, w[2 * g + 1] - h1);
            }
            *(uint4*)&Whi[wr][wc] = make_uint4(hw[0], hw[1], hw[2], hw[3]);
            *(uint4*)&Wlo[wr][wc] = make_uint4(lw[0], lw[1], lw[2], lw[3]);
        }
        __syncthreads();
        if (s < 15) {
            xa = ((const float4*)(Ap + (s + 1) * 16))[0];
            xb = ((const float4*)(Ap + (s + 1) * 16))[1];
            wa = ((const float4*)(Bp + (size_t)(s + 1) * 16 * HD))[0];
            wb = ((const float4*)(Bp + (size_t)(s + 1) * 16 * HD))[1];
        }
        u32 ahi[4], alo[4];
        ldsm_x4(ahi, smem_u32(&Xhi[m0 + lr][lc]));
        ldsm_x4(alo, smem_u32(&Xlo[m0 + lr][lc]));
#pragma unroll
        for (int half = 0; half < 2; half++) {
            u32 bh[16], bl[16];
#pragma unroll
            for (int g = 0; g < 4; g++) {
                ldsm_x4t(bh + 4 * g, smem_u32(&Whi[lr][half * 64 + g * 16 + lc]));
                ldsm_x4t(bl + 4 * g, smem_u32(&Wlo[lr][half * 64 + g * 16 + lc]));
            }
#pragma unroll
            for (int n2 = 0; n2 < 8; n2++) {
                int nb = half * 8 + n2;
                mma16816(c[nb], ahi, bh[2 * n2], bh[2 * n2 + 1]);
                mma16816(c[nb], alo, bh[2 * n2], bh[2 * n2 + 1]);
                mma16816(c[nb], ahi, bl[2 * n2], bl[2 * n2 + 1]);
            }
        }
        __syncthreads();
    }

    // --- epilogue: h planes + src/dst dots from fragments ---
    int r0 = lane >> 2, col0 = (lane & 3) * 2;
    int row0 = bm * 128 + m0 + r0;
    int row1 = row0 + 8;
    float ps[2][2] = {}, pd[2][2] = {};
#pragma unroll
    for (int nb = 0; nb < 16; nb++) {
        int hdl = nb >> 3;
        int cloc = (nb & 7) * 8 + col0;
        int hd = bn * 2 + hdl;
        float as0 = asrc[hd * DD + cloc], as1 = asrc[hd * DD + cloc + 1];
        float ad0 = adst[hd * DD + cloc], ad1 = adst[hd * DD + cloc + 1];
        float v0 = c[nb][0], v1 = c[nb][1], v2 = c[nb][2], v3 = c[nb][3];
        ps[0][hdl] += v0 * as0 + v1 * as1;
        ps[1][hdl] += v2 * as0 + v3 * as1;
        pd[0][hdl] += v0 * ad0 + v1 * ad1;
        pd[1][hdl] += v2 * ad0 + v3 * ad1;
        int gcol = bn * 128 + nb * 8 + col0;
        float h0 = bhi(v0), h1 = bhi(v1);
        *(u32*)&g_hbhi[(size_t)row0 * HD + gcol] = cvt2(h0, h1);
        *(u32*)&g_hblo[(size_t)row0 * HD + gcol] = cvt2(v0 - h0, v1 - h1);
        float h2 = bhi(v2), h3 = bhi(v3);
        *(u32*)&g_hbhi[(size_t)row1 * HD + gcol] = cvt2(h2, h3);
        *(u32*)&g_hblo[(size_t)row1 * HD + gcol] = cvt2(v2 - h2, v3 - h3);
    }
#pragma unroll
    for (int r = 0; r < 2; r++)
#pragma unroll
        for (int h = 0; h < 2; h++) {
            ps[r][h] += __shfl_xor_sync(0xffffffffu, ps[r][h], 1);
            ps[r][h] += __shfl_xor_sync(0xffffffffu, ps[r][h], 2);
            pd[r][h] += __shfl_xor_sync(0xffffffffu, pd[r][h], 1);
            pd[r][h] += __shfl_xor_sync(0xffffffffu, pd[r][h], 2);
        }
    if ((lane & 3) == 0) {
#pragma unroll
        for (int h = 0; h < 2; h++) {
            g_src[(size_t)row0 * HH + bn * 2 + h] = ps[0][h];
            g_src[(size_t)row1 * HH + bn * 2 + h] = ps[1][h];
            g_dst[(size_t)row0 * HH + bn * 2 + h] = pd[0][h];
            g_dst[(size_t)row1 * HH + bn * 2 + h] = pd[1][h];
        }
    }
}

// ---------------------------------------------------------------------------
// Kernel 2: attention. P computed DIRECTLY into mma A-fragment registers —
// no P smem round-trip, no score->mma barrier (warps overlap phases).
// Block = (128 i-rows, head, batch), 256 threads / 8 warps.
// Warp wid: m-block wid*16, all 64 d-cols. Thread lane: rows m0+lane/4,
// m0+lane/4+8; cols 2(lane%3..)+{0,1,8,9} per 16-wide k-step (A-frag map).
// ---------------------------------------------------------------------------
__global__ __launch_bounds__(256, 2) void attn_k(const int* __restrict__ adj,
                                                 const int* __restrict__ mask) {
    __shared__ __align__(16) u16 Vhi[64][72];
    __shared__ __align__(16) u16 Vlo[64][72];
    __shared__ float s_dst[64];
    __shared__ float s_l[128];

    int it = blockIdx.x, hh = blockIdx.y, b = blockIdx.z;
    int i0 = it * 128;
    int tid = threadIdx.x;
    int lane = tid & 31, wid = tid >> 5;
    int m0 = wid * 16;
    int q = lane & 3, rh = lane >> 2;
    int lr = lane & 15, lc = (lane >> 4) * 8;

    int gr0 = b * NN + i0 + m0 + rh;        // global row (lo half)
    int gr1 = gr0 + 8;                      // global row (hi half)
    float src0 = mask[gr0] > 0 ? g_src[(size_t)gr0 * HH + hh] : NEGBIG;
    float src1 = mask[gr1] > 0 ? g_src[(size_t)gr1 * HH + hh] : NEGBIG;
    const int* ar0 = adj + (size_t)gr0 * NN;
    const int* ar1 = adj + (size_t)gr1 * NN;

    float c[8][4] = {};
    float ls0 = 0.f, ls1 = 0.f;

    // V staging mapping
    int vj = tid >> 2, vc = (tid & 3) * 16;

    // prologue: prefetch tile 0 V + dst
    uint4 vh0, vh1, vl0, vl1;
    float dv = 0.f;
    {
        const uint4* hp = (const uint4*)(g_hbhi + (size_t)(b * NN + vj) * HD + hh * 64 + vc);
        const uint4* lp = (const uint4*)(g_hblo + (size_t)(b * NN + vj) * HD + hh * 64 + vc);
        vh0 = hp[0]; vh1 = hp[1];
        vl0 = lp[0]; vl1 = lp[1];
        if (tid < 64) {
            int gj = b * NN + tid;
            float d = g_dst[(size_t)gj * HH + hh];
            dv = mask[gj] > 0 ? d : NEGBIG;
        }
    }

    for (int t = 0; t < 16; t++) {
        int jt = t * 64;
        __syncthreads();                  // V tile free
        *(uint4*)&Vhi[vj][vc] = vh0;
        *(uint4*)&Vhi[vj][vc + 8] = vh1;
        *(uint4*)&Vlo[vj][vc] = vl0;
        *(uint4*)&Vlo[vj][vc + 8] = vl1;
        if (tid < 64) s_dst[tid] = dv;
        __syncthreads();                  // V + dst visible

        // --- score directly into A-fragments (hi/lo) ---
        u32 afh[16], afl[16];
        {
            // issue all adj loads first (MLP=16, L2-resident)
            int2 aj[16];
#pragma unroll
            for (int ks = 0; ks < 4; ks++) {
                int j0 = jt + ks * 16 + 2 * q;
                aj[4 * ks + 0] = *(const int2*)(ar0 + j0);
                aj[4 * ks + 1] = *(const int2*)(ar1 + j0);
                aj[4 * ks + 2] = *(const int2*)(ar0 + j0 + 8);
                aj[4 * ks + 3] = *(const int2*)(ar1 + j0 + 8);
            }
#pragma unroll
            for (int ks = 0; ks < 4; ks++) {
                float2 dA = *(const float2*)&s_dst[ks * 16 + 2 * q];
                float2 dB = *(const float2*)&s_dst[ks * 16 + 8 + 2 * q];
                int2 a00 = aj[4 * ks + 0], a10 = aj[4 * ks + 1];
                int2 a01 = aj[4 * ks + 2], a11 = aj[4 * ks + 3];
                float e, p00, p01, p02, p03, p10, p11, p12, p13;
                e = src0 + dA.x; e = fmaxf(e, 0.2f * e); p00 = a00.x > 0 ? __expf(e) : 0.f;
                e = src0 + dA.y; e = fmaxf(e, 0.2f * e); p01 = a00.y > 0 ? __expf(e) : 0.f;
                e = src1 + dA.x; e = fmaxf(e, 0.2f * e); p10 = a10.x > 0 ? __expf(e) : 0.f;
                e = src1 + dA.y; e = fmaxf(e, 0.2f * e); p11 = a10.y > 0 ? __expf(e) : 0.f;
                e = src0 + dB.x; e = fmaxf(e, 0.2f * e); p02 = a01.x > 0 ? __expf(e) : 0.f;
                e = src0 + dB.y; e = fmaxf(e, 0.2f * e); p03 = a01.y > 0 ? __expf(e) : 0.f;
                e = src1 + dB.x; e = fmaxf(e, 0.2f * e); p12 = a11.x > 0 ? __expf(e) : 0.f;
                e = src1 + dB.y; e = fmaxf(e, 0.2f * e); p13 = a11.y > 0 ? __expf(e) : 0.f;
                ls0 += (p00 + p01) + (p02 + p03);
                ls1 += (p10 + p11) + (p12 + p13);
                float h;
                h = bhi(p00); float h2 = bhi(p01);
                afh[4 * ks + 0] = cvt2(h, h2);
                afl[4 * ks + 0] = cvt2(p00 - h, p01 - h2);
                h = bhi(p10); h2 = bhi(p11);
                afh[4 * ks + 1] = cvt2(h, h2);
                afl[4 * ks + 1] = cvt2(p10 - h, p11 - h2);
                h = bhi(p02); h2 = bhi(p03);
                afh[4 * ks + 2] = cvt2(h, h2);
                afl[4 * ks + 2] = cvt2(p02 - h, p03 - h2);
                h = bhi(p12); h2 = bhi(p13);
                afh[4 * ks + 3] = cvt2(h, h2);
                afl[4 * ks + 3] = cvt2(p12 - h, p13 - h2);
            }
        }

        // prefetch next tile V + dst (lands during mma)
        if (t < 15) {
            const uint4* hp = (const uint4*)(g_hbhi + (size_t)(b * NN + jt + 64 + vj) * HD + hh * 64 + vc);
            const uint4* lp = (const uint4*)(g_hblo + (size_t)(b * NN + jt + 64 + vj) * HD + hh * 64 + vc);
            vh0 = hp[0]; vh1 = hp[1];
            vl0 = lp[0]; vl1 = lp[1];
            if (tid < 64) {
                int gj = b * NN + jt + 64 + tid;
                float d = g_dst[(size_t)gj * HH + hh];
                dv = mask[gj] > 0 ? d : NEGBIG;
            }
        }

        // --- mma: A in regs, B from smem, 3 passes ---
#pragma unroll
        for (int ks = 0; ks < 4; ks++) {
            u32 bh[16], bl[16];
            int br = ks * 16 + lr;
#pragma unroll
            for (int g = 0; g < 4; g++) {
                ldsm_x4t(bh + 4 * g, smem_u32(&Vhi[br][g * 16 + lc]));
                ldsm_x4t(bl + 4 * g, smem_u32(&Vlo[br][g * 16 + lc]));
            }
#pragma unroll
            for (int nb = 0; nb < 8; nb++) {
                mma16816(c[nb], afh + 4 * ks, bh[2 * nb], bh[2 * nb + 1]);
                mma16816(c[nb], afl + 4 * ks, bh[2 * nb], bh[2 * nb + 1]);
                mma16816(c[nb], afh + 4 * ks, bl[2 * nb], bl[2 * nb + 1]);
            }
        }
    }

    // --- final l reduction + epilogue ---
    ls0 += __shfl_xor_sync(0xffffffffu, ls0, 1);
    ls0 += __shfl_xor_sync(0xffffffffu, ls0, 2);
    ls1 += __shfl_xor_sync(0xffffffffu, ls1, 1);
    ls1 += __shfl_xor_sync(0xffffffffu, ls1, 2);
    if (q == 0) {
        s_l[m0 + rh] = ls0;
        s_l[m0 + rh + 8] = ls1;
    }
    __syncthreads();
    {
        int col0 = (lane & 3) * 2;
        float l0 = s_l[m0 + rh], l1 = s_l[m0 + rh + 8];
        float inv0 = l0 > 0.f ? 1.0f / l0 : 0.f;
        float inv1 = l1 > 0.f ? 1.0f / l1 : 0.f;
        float* ob = g_att + (size_t)gr0 * HD + hh * 64 + col0;
#pragma unroll
        for (int nb = 0; nb < 8; nb++) {
            *(float2*)(ob + nb * 8) = make_float2(c[nb][0] * inv0, c[nb][1] * inv0);
            *(float2*)(ob + 8 * HD + nb * 8) = make_float2(c[nb][2] * inv1, c[nb][3] * inv1);
        }
    }
}

// ---------------------------------------------------------------------------
// Kernel 3: LayerNorm. 32 threads/row, warp-shfl only.  (unchanged)
// ---------------------------------------------------------------------------
__global__ __launch_bounds__(256) void ln_k(const int* __restrict__ mask,
                                            const float* __restrict__ gamma,
                                            const float* __restrict__ beta,
                                            float* __restrict__ out) {
    int row = blockIdx.x * 8 + (threadIdx.x >> 5);
    int lane = threadIdx.x & 31;
    float mf = mask[row] > 0 ? 1.f : 0.f;
    const float* ar = g_att + (size_t)row * HD + lane * 8;
    float4 v0 = ((const float4*)ar)[0];
    float4 v1 = ((const float4*)ar)[1];
    v0.x *= mf; v0.y *= mf; v0.z *= mf; v0.w *= mf;
    v1.x *= mf; v1.y *= mf; v1.z *= mf; v1.w *= mf;
    float s = v0.x + v0.y + v0.z + v0.w + v1.x + v1.y + v1.z + v1.w;
    float s2 = v0.x * v0.x + v0.y * v0.y + v0.z * v0.z + v0.w * v0.w
             + v1.x * v1.x + v1.y * v1.y + v1.z * v1.z + v1.w * v1.w;
#pragma unroll
    for (int o = 16; o > 0; o >>= 1) {
        s += __shfl_xor_sync(0xffffffffu, s, o);
        s2 += __shfl_xor_sync(0xffffffffu, s2, o);
    }
    float mu = s * (1.0f / HD);
    float var = s2 * (1.0f / HD) - mu * mu;
    float rstd = rsqrtf(var + EPSV);
    float4 g0 = ((const float4*)(gamma + lane * 8))[0];
    float4 g1 = ((const float4*)(gamma + lane * 8))[1];
    float4 b0 = ((const float4*)(beta + lane * 8))[0];
    float4 b1 = ((const float4*)(beta + lane * 8))[1];
    float* o = out + (size_t)row * HD + lane * 8;
    ((float4*)o)[0] = make_float4((v0.x - mu) * rstd * g0.x + b0.x,
                                  (v0.y - mu) * rstd * g0.y + b0.y,
                                  (v0.z - mu) * rstd * g0.z + b0.z,
                                  (v0.w - mu) * rstd * g0.w + b0.w);
    ((float4*)o)[1] = make_float4((v1.x - mu) * rstd * g1.x + b1.x,
                                  (v1.y - mu) * rstd * g1.y + b1.y,
                                  (v1.z - mu) * rstd * g1.z + b1.z,
                                  (v1.w - mu) * rstd * g1.w + b1.w);
}

// ---------------------------------------------------------------------------
extern "C" void kernel_launch(void* const* d_in, const int* in_sizes, int n_in,
                              void* d_out, int out_size) {
    const float* x = (const float*)d_in[0];
    const int* adj = (const int*)d_in[1];
    const int* mask = (const int*)d_in[2];
    const float* Wm = (const float*)d_in[3];
    const float* a_src = (const float*)d_in[4];
    const float* a_dst = (const float*)d_in[5];
    const float* gamma = (const float*)d_in[6];
    const float* beta = (const float*)d_in[7];
    float* out = (float*)d_out;

    dim3 gg(BB * NN / 128, HD / 128);
    gemm_k<<<gg, 256>>>(x, Wm, a_src, a_dst);
    dim3 ga(NN / 128, HH, BB);
    attn_k<<<ga, 256>>>(adj, mask);
    ln_k<<<BB * NN / 8, 256>>>(mask, gamma, beta, out);
}